// round 1
// baseline (speedup 1.0000x reference)
#include <cuda_runtime.h>

#define SPARSITY 0.01f

// Dimensions are fixed for this problem.
#define BATCH 8
#define NN    2048      // nodes
#define DIN   256
#define DOUT  256

// Scratch for support = x @ quantize(W): [B*N, DOUT] fp32 = 16.8 MB
__device__ float g_support[BATCH * NN * DOUT];

// Tiling
#define BM 64
#define BN 64
#define BK 16

__device__ __forceinline__ float quant(float w) {
    // ternary: +s if w > s, -s if w < -s, else 0
    return (w > SPARSITY ? SPARSITY : 0.0f) + (w < -SPARSITY ? -SPARSITY : 0.0f);
}

// C[M,N] = A[M,K] @ quantize(W[K,N]);  M=16384, K=256, N=256
__global__ void __launch_bounds__(256) gemm_support_kernel(
    const float* __restrict__ A,   // x, [M, K]
    const float* __restrict__ W,   // weight, [K, N]
    float* __restrict__ C)         // support, [M, N]
{
    const int M_stride = DIN;   // K for A
    const int N = DOUT;

    __shared__ float As[BK][BM];
    __shared__ float Bs[BK][BN];

    const int t  = threadIdx.x;
    const int bm = blockIdx.x * BM;
    const int bn = blockIdx.y * BN;

    // A tile load mapping: 64 rows x 16 cols, one float4 per thread
    const int arow = t >> 2;              // 0..63
    const int acol = (t & 3) << 2;        // 0,4,8,12
    // B tile load mapping: 16 rows x 64 cols, one float4 per thread
    const int brow = t >> 4;              // 0..15
    const int bcol = (t & 15) << 2;       // 0..60

    const int tx = t & 15;                // 0..15 (col group)
    const int ty = t >> 4;                // 0..15 (row group)

    float acc[4][4] = {};

    for (int k0 = 0; k0 < DIN; k0 += BK) {
        float4 av = *(const float4*)(A + (size_t)(bm + arow) * M_stride + k0 + acol);
        As[acol + 0][arow] = av.x;
        As[acol + 1][arow] = av.y;
        As[acol + 2][arow] = av.z;
        As[acol + 3][arow] = av.w;

        float4 bv = *(const float4*)(W + (size_t)(k0 + brow) * N + bn + bcol);
        bv.x = quant(bv.x); bv.y = quant(bv.y); bv.z = quant(bv.z); bv.w = quant(bv.w);
        *(float4*)&Bs[brow][bcol] = bv;

        __syncthreads();

        #pragma unroll
        for (int k = 0; k < BK; k++) {
            float a[4], b[4];
            *(float4*)a = *(const float4*)&As[k][ty << 2];
            *(float4*)b = *(const float4*)&Bs[k][tx << 2];
            #pragma unroll
            for (int i = 0; i < 4; i++)
                #pragma unroll
                for (int j = 0; j < 4; j++)
                    acc[i][j] = fmaf(a[i], b[j], acc[i][j]);
        }
        __syncthreads();
    }

    #pragma unroll
    for (int i = 0; i < 4; i++) {
        float4 v = make_float4(acc[i][0], acc[i][1], acc[i][2], acc[i][3]);
        *(float4*)(C + (size_t)(bm + (ty << 2) + i) * N + bn + (tx << 2)) = v;
    }
}

// out[b][m][n] = relu( sum_k adj[b][m][k] * support[b][k][n] + bias[n] )
// per-batch: M=2048, K=2048, N=256
__global__ void __launch_bounds__(256) gemm_adj_kernel(
    const float* __restrict__ adj,      // [B, NN, NN]
    const float* __restrict__ support,  // [B, NN, DOUT]
    const float* __restrict__ bias,     // [DOUT]
    float* __restrict__ out)            // [B, NN, DOUT]
{
    const int b = blockIdx.z;
    const float* A = adj + (size_t)b * NN * NN;
    const float* Bm = support + (size_t)b * NN * DOUT;
    float* C = out + (size_t)b * NN * DOUT;

    const int K = NN;      // 2048
    const int N = DOUT;    // 256

    __shared__ float As[BK][BM];
    __shared__ float Bs[BK][BN];

    const int t  = threadIdx.x;
    const int bm = blockIdx.x * BM;
    const int bn = blockIdx.y * BN;

    const int arow = t >> 2;
    const int acol = (t & 3) << 2;
    const int brow = t >> 4;
    const int bcol = (t & 15) << 2;

    const int tx = t & 15;
    const int ty = t >> 4;

    float acc[4][4] = {};

    for (int k0 = 0; k0 < K; k0 += BK) {
        float4 av = *(const float4*)(A + (size_t)(bm + arow) * K + k0 + acol);
        As[acol + 0][arow] = av.x;
        As[acol + 1][arow] = av.y;
        As[acol + 2][arow] = av.z;
        As[acol + 3][arow] = av.w;

        float4 bv = *(const float4*)(Bm + (size_t)(k0 + brow) * N + bn + bcol);
        *(float4*)&Bs[brow][bcol] = bv;

        __syncthreads();

        #pragma unroll
        for (int k = 0; k < BK; k++) {
            float a[4], bb[4];
            *(float4*)a  = *(const float4*)&As[k][ty << 2];
            *(float4*)bb = *(const float4*)&Bs[k][tx << 2];
            #pragma unroll
            for (int i = 0; i < 4; i++)
                #pragma unroll
                for (int j = 0; j < 4; j++)
                    acc[i][j] = fmaf(a[i], bb[j], acc[i][j]);
        }
        __syncthreads();
    }

    // epilogue: + bias, relu
    const int cn = bn + (tx << 2);
    float4 bv4 = *(const float4*)(bias + cn);
    const float bb4[4] = {bv4.x, bv4.y, bv4.z, bv4.w};

    #pragma unroll
    for (int i = 0; i < 4; i++) {
        float4 v;
        v.x = fmaxf(acc[i][0] + bb4[0], 0.0f);
        v.y = fmaxf(acc[i][1] + bb4[1], 0.0f);
        v.z = fmaxf(acc[i][2] + bb4[2], 0.0f);
        v.w = fmaxf(acc[i][3] + bb4[3], 0.0f);
        *(float4*)(C + (size_t)(bm + (ty << 2) + i) * N + cn) = v;
    }
}

extern "C" void kernel_launch(void* const* d_in, const int* in_sizes, int n_in,
                              void* d_out, int out_size) {
    const float* x      = (const float*)d_in[0];  // [8, 2048, 256]
    const float* adj    = (const float*)d_in[1];  // [8, 2048, 2048]
    const float* weight = (const float*)d_in[2];  // [256, 256]
    const float* bias   = (const float*)d_in[3];  // [256]
    float* out = (float*)d_out;                   // [8, 2048, 256]

    float* support;
    cudaGetSymbolAddress((void**)&support, g_support);

    // GEMM 1: support = x @ quantize(W)   (M = 8*2048 = 16384)
    {
        dim3 grid((BATCH * NN) / BM, DOUT / BN, 1);
        gemm_support_kernel<<<grid, 256>>>(x, weight, support);
    }
    // GEMM 2: out = relu(adj @ support + bias), per batch
    {
        dim3 grid(NN / BM, DOUT / BN, BATCH);
        gemm_adj_kernel<<<grid, 256>>>(adj, support, bias, out);
    }
}

// round 3
// speedup vs baseline: 3.1069x; 3.1069x over previous
#include <cuda_runtime.h>
#include <cstdint>

#define SPARSITY 0.01f
#define BATCH 8
#define NN    2048
#define DIN   256
#define DOUT  256

// support, transposed to [b][col][node], values pre-rounded to tf32
__device__ float g_ST[BATCH * DOUT * NN];

__device__ __forceinline__ uint32_t smem_u32(const void* p) {
    uint32_t a;
    asm("{ .reg .u64 t; cvta.to.shared.u64 t, %1; cvt.u32.u64 %0, t; }"
        : "=r"(a) : "l"(p));
    return a;
}
__device__ __forceinline__ float to_tf32(float v) {
    float r;
    asm("cvt.rna.tf32.f32 %0, %1;" : "=f"(r) : "f"(v));
    return r;
}
__device__ __forceinline__ float quant(float w) {
    return (w > SPARSITY ? SPARSITY : 0.0f) + (w < -SPARSITY ? -SPARSITY : 0.0f);
}

// ============================================================================
// GEMM 1: support = x @ quantize(W).  SIMT fp32, transposed tf32-rounded store.
// ============================================================================
#define BM1 64
#define BN1 64
#define BK1 16

__global__ void __launch_bounds__(256) gemm_support_kernel(
    const float* __restrict__ A,   // x, [16384, 256]
    const float* __restrict__ W,   // weight, [256, 256]
    float* __restrict__ ST)        // [b][col][node]
{
    __shared__ float As[BK1][BM1];
    __shared__ float Bs[BK1][BN1];
    __shared__ float stage[BN1][BM1 + 4];   // [col][node], padded

    const int t  = threadIdx.x;
    const int bm = blockIdx.x * BM1;
    const int bn = blockIdx.y * BN1;

    const int arow = t >> 2;
    const int acol = (t & 3) << 2;
    const int brow = t >> 4;
    const int bcol = (t & 15) << 2;
    const int tx = t & 15;
    const int ty = t >> 4;

    float acc[4][4] = {};

    for (int k0 = 0; k0 < DIN; k0 += BK1) {
        float4 av = *(const float4*)(A + (size_t)(bm + arow) * DIN + k0 + acol);
        As[acol + 0][arow] = av.x;
        As[acol + 1][arow] = av.y;
        As[acol + 2][arow] = av.z;
        As[acol + 3][arow] = av.w;

        float4 bv = *(const float4*)(W + (size_t)(k0 + brow) * DOUT + bn + bcol);
        bv.x = quant(bv.x); bv.y = quant(bv.y); bv.z = quant(bv.z); bv.w = quant(bv.w);
        *(float4*)&Bs[brow][bcol] = bv;

        __syncthreads();

        #pragma unroll
        for (int k = 0; k < BK1; k++) {
            float a[4], b[4];
            *(float4*)a = *(const float4*)&As[k][ty << 2];
            *(float4*)b = *(const float4*)&Bs[k][tx << 2];
            #pragma unroll
            for (int i = 0; i < 4; i++)
                #pragma unroll
                for (int j = 0; j < 4; j++)
                    acc[i][j] = fmaf(a[i], b[j], acc[i][j]);
        }
        __syncthreads();
    }

    // stage (tf32-rounded) transposed: stage[col][node]
    #pragma unroll
    for (int i = 0; i < 4; i++)
        #pragma unroll
        for (int j = 0; j < 4; j++)
            stage[(tx << 2) + j][(ty << 2) + i] = to_tf32(acc[i][j]);
    __syncthreads();

    // coalesced store: thread -> (col = t/4, 16 nodes at (t%4)*16)
    const int colL = t >> 2;
    const int nb   = (t & 3) << 4;
    const int b    = bm >> 11;
    const int node0 = bm & (NN - 1);
    float* dst = ST + ((size_t)(b * DOUT + bn + colL) << 11) + node0 + nb;
    #pragma unroll
    for (int v = 0; v < 4; v++)
        *(float4*)(dst + v * 4) = *(const float4*)&stage[colL][nb + v * 4];
}

// ============================================================================
// GEMM 2: out = relu(adj @ support + bias) via mma.sync tf32.
// CTA tile 64(M) x 256(N) x 32(K). 8 warps: 2(M) x 4(N), warp tile 32x64.
// ============================================================================
#define TM 64
#define TN 256
#define TK 32
#define KIT (NN / TK)   // 64

// smem offsets (bytes): As[2][64][32]f32 swizzled, Bs[2][256][32]f32 swizzled
#define AS_BYTES (TM * TK * 4)      // 8192
#define BS_BYTES (TN * TK * 4)      // 32768
#define SM_A(p)  ((p) * AS_BYTES)
#define SM_B(p)  (2 * AS_BYTES + (p) * BS_BYTES)
#define SM2_TOTAL (2 * AS_BYTES + 2 * BS_BYTES)  // 81920

// swizzled byte offset within a tile: row (128B each), chunk = 16B unit 0..7
__device__ __forceinline__ uint32_t swz(int row, int chunk) {
    return (uint32_t)(row * 128 + ((chunk ^ (row & 7)) << 4));
}

__device__ __forceinline__ void ldsm4(uint32_t& r0, uint32_t& r1, uint32_t& r2,
                                      uint32_t& r3, uint32_t addr) {
    asm volatile("ldmatrix.sync.aligned.m8n8.x4.shared.b16 {%0,%1,%2,%3}, [%4];"
                 : "=r"(r0), "=r"(r1), "=r"(r2), "=r"(r3) : "r"(addr));
}
__device__ __forceinline__ void mma_tf32(float* d, uint32_t a0, uint32_t a1,
                                         uint32_t a2, uint32_t a3,
                                         uint32_t b0, uint32_t b1) {
    asm volatile(
        "mma.sync.aligned.m16n8k8.row.col.f32.tf32.tf32.f32 "
        "{%0,%1,%2,%3}, {%4,%5,%6,%7}, {%8,%9}, {%0,%1,%2,%3};"
        : "+f"(d[0]), "+f"(d[1]), "+f"(d[2]), "+f"(d[3])
        : "r"(a0), "r"(a1), "r"(a2), "r"(a3), "r"(b0), "r"(b1));
}

__global__ void __launch_bounds__(256, 2) gemm2_mma_kernel(
    const float* __restrict__ adj,
    const float* __restrict__ ST,    // [b][n][k] tf32-rounded
    const float* __restrict__ bias,
    float* __restrict__ out)
{
    extern __shared__ char smem[];
    const uint32_t sb = smem_u32(smem);

    const int t    = threadIdx.x;
    const int wid  = t >> 5;
    const int lane = t & 31;
    const int bm   = blockIdx.x * TM;
    const int b    = blockIdx.y;

    const int warp_m = wid & 1;        // 0..1
    const int warp_n = wid >> 1;       // 0..3
    const int M0 = warp_m * 32;
    const int N0 = warp_n * 64;

    const float* Ag = adj + (size_t)b * NN * NN;
    const float* Bg = ST + ((size_t)b * DOUT << 11);

    float acc[2][8][4] = {};   // [m-frag][n-frag][c0..c3]

    // ---- A staging: 2 float4 per thread ----
    const int a_row = t >> 3;          // 0..31  (2 iters -> 64 rows? no: idx below)
    float4 areg[2];

    auto loadA = [&](int it) {
        const int k0 = it * TK;
        #pragma unroll
        for (int i = 0; i < 2; i++) {
            int idx = t + 256 * i;         // 0..511
            int r = idx >> 3;              // 0..63
            int c = idx & 7;
            areg[i] = *(const float4*)(Ag + (size_t)(bm + r) * NN + k0 + (c << 2));
        }
    };
    auto storeA = [&](int p) {
        #pragma unroll
        for (int i = 0; i < 2; i++) {
            int idx = t + 256 * i;
            int r = idx >> 3;
            int c = idx & 7;
            float4 v = areg[i];
            v.x = to_tf32(v.x); v.y = to_tf32(v.y);
            v.z = to_tf32(v.z); v.w = to_tf32(v.w);
            *(float4*)(smem + SM_A(p) + swz(r, c)) = v;
        }
    };
    auto loadB_async = [&](int it, int p) {
        const int k0 = it * TK;
        #pragma unroll
        for (int i = 0; i < 8; i++) {
            int idx = t + 256 * i;         // 0..2047
            int r = idx >> 3;              // n-row 0..255
            int c = idx & 7;
            uint32_t dst = sb + SM_B(p) + swz(r, c);
            const float* src = Bg + ((size_t)r << 11) + k0 + (c << 2);
            asm volatile("cp.async.cg.shared.global [%0], [%1], 16;"
                         :: "r"(dst), "l"(src));
        }
        asm volatile("cp.async.commit_group;");
    };

    // ---- prologue ----
    loadA(0);
    loadB_async(0, 0);
    storeA(0);
    asm volatile("cp.async.wait_group 0;");
    __syncthreads();

    // ---- main loop ----
    for (int it = 0; it < KIT; it++) {
        const int p = it & 1;
        if (it + 1 < KIT) {
            loadA(it + 1);
            loadB_async(it + 1, 1 - p);
        }

        const uint32_t abase = sb + SM_A(p);
        const uint32_t bbase = sb + SM_B(p);

        #pragma unroll
        for (int ks = 0; ks < 4; ks++) {
            // A fragments: 2 m-frags via one ldsm.x4 each
            uint32_t a[2][4];
            #pragma unroll
            for (int mf = 0; mf < 2; mf++) {
                int q = lane >> 3;
                int row = M0 + mf * 16 + (lane & 7) + ((q & 1) << 3);
                int ch  = 2 * ks + (q >> 1);
                ldsm4(a[mf][0], a[mf][1], a[mf][2], a[mf][3], abase + swz(row, ch));
            }
            // B fragments: 8 n-frags, 2 per ldsm.x4
            uint32_t bfr[8][2];
            #pragma unroll
            for (int j8 = 0; j8 < 4; j8++) {
                int q = lane >> 3;
                int row = N0 + j8 * 16 + ((q >> 1) << 3) + (lane & 7);
                int ch  = 2 * ks + (q & 1);
                uint32_t r0, r1, r2, r3;
                ldsm4(r0, r1, r2, r3, bbase + swz(row, ch));
                bfr[j8 * 2 + 0][0] = r0; bfr[j8 * 2 + 0][1] = r1;
                bfr[j8 * 2 + 1][0] = r2; bfr[j8 * 2 + 1][1] = r3;
            }
            #pragma unroll
            for (int mf = 0; mf < 2; mf++)
                #pragma unroll
                for (int nf = 0; nf < 8; nf++)
                    mma_tf32(acc[mf][nf], a[mf][0], a[mf][1], a[mf][2], a[mf][3],
                             bfr[nf][0], bfr[nf][1]);
        }

        if (it + 1 < KIT) {
            storeA(1 - p);
            asm volatile("cp.async.wait_group 0;");
        }
        __syncthreads();
    }

    // ---- epilogue: bias + relu, float2 stores ----
    const int rq = lane >> 2;         // 0..7
    const int cq = lane & 3;          // 0..3
    #pragma unroll
    for (int nf = 0; nf < 8; nf++) {
        const int col = N0 + nf * 8 + (cq << 1);
        const float2 bv = *(const float2*)(bias + col);
        #pragma unroll
        for (int mf = 0; mf < 2; mf++) {
            const int row = bm + M0 + mf * 16 + rq;
            float* o0 = out + ((size_t)b * NN + row) * DOUT + col;
            float2 v0, v1;
            v0.x = fmaxf(acc[mf][nf][0] + bv.x, 0.0f);
            v0.y = fmaxf(acc[mf][nf][1] + bv.y, 0.0f);
            v1.x = fmaxf(acc[mf][nf][2] + bv.x, 0.0f);
            v1.y = fmaxf(acc[mf][nf][3] + bv.y, 0.0f);
            *(float2*)o0 = v0;
            *(float2*)(o0 + 8 * DOUT) = v1;
        }
    }
}

// ============================================================================
extern "C" void kernel_launch(void* const* d_in, const int* in_sizes, int n_in,
                              void* d_out, int out_size) {
    const float* x      = (const float*)d_in[0];
    const float* adj    = (const float*)d_in[1];
    const float* weight = (const float*)d_in[2];
    const float* bias   = (const float*)d_in[3];
    float* out = (float*)d_out;

    float* ST;
    cudaGetSymbolAddress((void**)&ST, g_ST);

    {
        dim3 grid((BATCH * NN) / BM1, DOUT / BN1, 1);
        gemm_support_kernel<<<grid, 256>>>(x, weight, ST);
    }
    {
        cudaFuncSetAttribute(gemm2_mma_kernel,
                             cudaFuncAttributeMaxDynamicSharedMemorySize, SM2_TOTAL);
        dim3 grid(NN / TM, BATCH, 1);
        gemm2_mma_kernel<<<grid, 256, SM2_TOTAL>>>(adj, ST, bias, out);
    }
}

// round 5
// speedup vs baseline: 3.1271x; 1.0065x over previous
#include <cuda_runtime.h>
#include <cstdint>

#define SPARSITY 0.01f
#define BATCH 8
#define NN    2048
#define DIN   256
#define DOUT  256

// support^T: [b][col][node], tf32-rounded
__device__ float g_ST[BATCH * DOUT * NN];
// quantize(W)^T: [Dout][Din], tf32-rounded
__device__ float g_WT[DOUT * DIN];

__device__ __forceinline__ uint32_t smem_u32(const void* p) {
    uint32_t a;
    asm("{ .reg .u64 t; cvta.to.shared.u64 t, %1; cvt.u32.u64 %0, t; }"
        : "=r"(a) : "l"(p));
    return a;
}
__device__ __forceinline__ float to_tf32(float v) {
    float r;
    asm("cvt.rna.tf32.f32 %0, %1;" : "=f"(r) : "f"(v));
    return r;
}
__device__ __forceinline__ float quant(float w) {
    return (w > SPARSITY ? SPARSITY : 0.0f) + (w < -SPARSITY ? -SPARSITY : 0.0f);
}

// ---------------- W transpose + quantize + tf32 round (tiny) ----------------
__global__ void quantW_kernel(const float* __restrict__ W, float* __restrict__ WT) {
    __shared__ float tile[32][33];
    const int tx = threadIdx.x, ty = threadIdx.y;
    const int o0 = blockIdx.x * 32;   // Dout block
    const int i0 = blockIdx.y * 32;   // Din block
    #pragma unroll
    for (int j = ty; j < 32; j += 8)
        tile[j][tx] = quant(W[(size_t)(i0 + j) * DOUT + o0 + tx]);
    __syncthreads();
    #pragma unroll
    for (int j = ty; j < 32; j += 8)
        WT[(size_t)(o0 + j) * DIN + i0 + tx] = to_tf32(tile[tx][j]);
}

// ============================================================================
// Shared tf32 mma.sync GEMM: C[M,N] (+bias, relu) = A[M,K] @ B[N,K]^T
// CTA tile 128(M) x 256(N) x 32(K); 512 threads, 16 warps = 4(M) x 4(N),
// warp tile 32x64. 4-stage cp.async pipeline, HMMA truncates fp32->tf32.
// ============================================================================
#define TK 32
#define AS_BYTES (128 * TK * 4)              // 16384
#define BS_BYTES (256 * TK * 4)              // 32768
#define STAGE    (AS_BYTES + BS_BYTES)       // 49152
#define NSTAGE   4
#define SM_TOTAL (NSTAGE * STAGE)            // 196608

__device__ __forceinline__ uint32_t swz(int row, int chunk) {
    return (uint32_t)(row * 128 + ((chunk ^ (row & 7)) << 4));
}
__device__ __forceinline__ void ldsm4(uint32_t& r0, uint32_t& r1, uint32_t& r2,
                                      uint32_t& r3, uint32_t addr) {
    asm volatile("ldmatrix.sync.aligned.m8n8.x4.shared.b16 {%0,%1,%2,%3}, [%4];"
                 : "=r"(r0), "=r"(r1), "=r"(r2), "=r"(r3) : "r"(addr));
}
__device__ __forceinline__ void mma_tf32(float* d, uint32_t a0, uint32_t a1,
                                         uint32_t a2, uint32_t a3,
                                         uint32_t b0, uint32_t b1) {
    asm volatile(
        "mma.sync.aligned.m16n8k8.row.col.f32.tf32.tf32.f32 "
        "{%0,%1,%2,%3}, {%4,%5,%6,%7}, {%8,%9}, {%0,%1,%2,%3};"
        : "+f"(d[0]), "+f"(d[1]), "+f"(d[2]), "+f"(d[3])
        : "r"(a0), "r"(a1), "r"(a2), "r"(a3), "r"(b0), "r"(b1));
}
__device__ __forceinline__ void cpasync16(uint32_t dst, const void* src) {
    asm volatile("cp.async.cg.shared.global [%0], [%1], 16;" :: "r"(dst), "l"(src));
}

template<int KITERS, bool RELU, bool TF32OUT>
__global__ void __launch_bounds__(512, 1) mm_tf32_kernel(
    const float* __restrict__ Abase, size_t batchA, int lda,
    const float* __restrict__ Bbase, size_t batchB, int ldb,
    float* __restrict__ Cbase, size_t batchC, int ldc,
    const float* __restrict__ bias)
{
    extern __shared__ char smem[];
    const uint32_t sb = smem_u32(smem);

    const int t    = threadIdx.x;
    const int wid  = t >> 5;
    const int lane = t & 31;
    const int bm   = blockIdx.x * 128;
    const int bn   = blockIdx.y * 256;
    const int b    = blockIdx.z;

    const float* Ag = Abase + (size_t)b * batchA;
    const float* Bg = Bbase + (size_t)b * batchB;
    float*       Cg = Cbase + (size_t)b * batchC;

    const int M0 = (wid & 3) * 32;
    const int N0 = (wid >> 2) * 64;

    float acc[2][8][4] = {};

    auto load_stage = [&](int it, int slot) {
        const int k0 = it * TK;
        const uint32_t s0 = sb + slot * STAGE;
        #pragma unroll
        for (int i = 0; i < 2; i++) {              // A: 128x32
            int idx = t + 512 * i;                 // 0..1023
            int r = idx >> 3, c = idx & 7;
            cpasync16(s0 + swz(r, c), Ag + (size_t)(bm + r) * lda + k0 + (c << 2));
        }
        #pragma unroll
        for (int i = 0; i < 4; i++) {              // B: 256x32
            int idx = t + 512 * i;                 // 0..2047
            int r = idx >> 3, c = idx & 7;
            cpasync16(s0 + AS_BYTES + swz(r, c),
                      Bg + (size_t)(bn + r) * ldb + k0 + (c << 2));
        }
        asm volatile("cp.async.commit_group;");
    };

    // prologue: fill 3 stages
    load_stage(0, 0);
    load_stage(1, 1);
    load_stage(2, 2);

    // lane-derived ldsm row bases (iter-invariant)
    const int q = lane >> 3;
    const int rA0 = M0 + (lane & 7) + ((q & 1) << 3);
    const int rB0 = N0 + ((q >> 1) << 3) + (lane & 7);

    for (int it = 0; it < KITERS; it++) {
        asm volatile("cp.async.wait_group 2;");
        __syncthreads();

        if (it + 3 < KITERS) load_stage(it + 3, (it + 3) & (NSTAGE - 1));
        else asm volatile("cp.async.commit_group;");   // keep group count uniform

        const uint32_t abase = sb + (it & (NSTAGE - 1)) * STAGE;
        const uint32_t bbase = abase + AS_BYTES;

        #pragma unroll
        for (int ks = 0; ks < 4; ks++) {
            uint32_t a[2][4];
            #pragma unroll
            for (int mf = 0; mf < 2; mf++) {
                int row = rA0 + mf * 16;
                int ch  = 2 * ks + (q >> 1);
                ldsm4(a[mf][0], a[mf][1], a[mf][2], a[mf][3], abase + swz(row, ch));
            }
            uint32_t bfr[8][2];
            #pragma unroll
            for (int j8 = 0; j8 < 4; j8++) {
                int row = rB0 + j8 * 16;
                int ch  = 2 * ks + (q & 1);
                uint32_t r0, r1, r2, r3;
                ldsm4(r0, r1, r2, r3, bbase + swz(row, ch));
                bfr[j8 * 2 + 0][0] = r0; bfr[j8 * 2 + 0][1] = r1;
                bfr[j8 * 2 + 1][0] = r2; bfr[j8 * 2 + 1][1] = r3;
            }
            #pragma unroll
            for (int mf = 0; mf < 2; mf++)
                #pragma unroll
                for (int nf = 0; nf < 8; nf++)
                    mma_tf32(acc[mf][nf], a[mf][0], a[mf][1], a[mf][2], a[mf][3],
                             bfr[nf][0], bfr[nf][1]);
        }
        __syncthreads();
    }

    // ---- epilogue ----
    const int rq = lane >> 2;
    const int cq = lane & 3;
    #pragma unroll
    for (int nf = 0; nf < 8; nf++) {
        const int col = bn + N0 + nf * 8 + (cq << 1);
        float2 bv = make_float2(0.f, 0.f);
        if (RELU) bv = *(const float2*)(bias + col);
        #pragma unroll
        for (int mf = 0; mf < 2; mf++) {
            const int row = bm + M0 + mf * 16 + rq;
            float* o0 = Cg + (size_t)row * ldc + col;
            float v0 = acc[mf][nf][0], v1 = acc[mf][nf][1];
            float v2 = acc[mf][nf][2], v3 = acc[mf][nf][3];
            if (RELU) {
                v0 = fmaxf(v0 + bv.x, 0.0f); v1 = fmaxf(v1 + bv.y, 0.0f);
                v2 = fmaxf(v2 + bv.x, 0.0f); v3 = fmaxf(v3 + bv.y, 0.0f);
            }
            if (TF32OUT) {
                v0 = to_tf32(v0); v1 = to_tf32(v1);
                v2 = to_tf32(v2); v3 = to_tf32(v3);
            }
            *(float2*)o0 = make_float2(v0, v1);
            *(float2*)(o0 + 8 * (size_t)ldc) = make_float2(v2, v3);
        }
    }
}

// ============================================================================
extern "C" void kernel_launch(void* const* d_in, const int* in_sizes, int n_in,
                              void* d_out, int out_size) {
    const float* x      = (const float*)d_in[0];  // [8, 2048, 256]
    const float* adj    = (const float*)d_in[1];  // [8, 2048, 2048]
    const float* weight = (const float*)d_in[2];  // [256, 256]
    const float* bias   = (const float*)d_in[3];  // [256]
    float* out = (float*)d_out;                   // [8, 2048, 256]

    float *ST, *WT;
    cudaGetSymbolAddress((void**)&ST, g_ST);
    cudaGetSymbolAddress((void**)&WT, g_WT);

    // 0) WT = tf32(quantize(W))^T   [Dout, Din]
    quantW_kernel<<<dim3(DOUT / 32, DIN / 32), dim3(32, 8)>>>(weight, WT);

    // 1) ST[b] = WT @ x[b]^T : M=Dout(256), N=nodes(2048), K=Din(256)
    {
        auto k = mm_tf32_kernel<DIN / TK, false, true>;
        cudaFuncSetAttribute(k, cudaFuncAttributeMaxDynamicSharedMemorySize, SM_TOTAL);
        dim3 grid(DOUT / 128, NN / 256, BATCH);
        k<<<grid, 512, SM_TOTAL>>>(
            WT, 0, DIN,                                   // A: shared across batch
            x, (size_t)NN * DIN, DIN,                     // B: x[b], rows=node, K-major
            ST, (size_t)DOUT * NN, NN,                    // C: ST[b][col][node]
            nullptr);
    }
    // 2) out[b] = relu(adj[b] @ ST[b]^T + bias) : M=2048, N=256, K=2048
    {
        auto k = mm_tf32_kernel<NN / TK, true, false>;
        cudaFuncSetAttribute(k, cudaFuncAttributeMaxDynamicSharedMemorySize, SM_TOTAL);
        dim3 grid(NN / 128, DOUT / 256, BATCH);
        k<<<grid, 512, SM_TOTAL>>>(
            adj, (size_t)NN * NN, NN,
            ST, (size_t)DOUT * NN, NN,
            out, (size_t)NN * DOUT, DOUT,
            bias);
    }
}

// round 6
// speedup vs baseline: 6.8873x; 2.2025x over previous
#include <cuda_runtime.h>
#include <cuda_fp16.h>
#include <cstdint>

#define SPARSITY 0.01f
#define BATCH 8
#define NN    2048
#define DIN   256
#define DOUT  256

// support^T as fp16: [b][col][node]
__device__ __half g_ST[BATCH * DOUT * NN];
// sign(quantize(W))^T as fp16 (+1/0/-1): [Dout][Din]
__device__ __half g_WT[DOUT * DIN];
// x as fp16: [b][node][din]
__device__ __half g_X16[BATCH * NN * DIN];

__device__ __forceinline__ uint32_t smem_u32(const void* p) {
    uint32_t a;
    asm("{ .reg .u64 t; cvta.to.shared.u64 t, %1; cvt.u32.u64 %0, t; }"
        : "=r"(a) : "l"(p));
    return a;
}

// ---------------- tiny prep kernels ----------------
__global__ void quantW_kernel(const float* __restrict__ W, __half* __restrict__ WT) {
    __shared__ float tile[32][33];
    const int tx = threadIdx.x, ty = threadIdx.y;
    const int o0 = blockIdx.x * 32;   // Dout block
    const int i0 = blockIdx.y * 32;   // Din block
    #pragma unroll
    for (int j = ty; j < 32; j += 8) {
        float w = W[(size_t)(i0 + j) * DOUT + o0 + tx];
        tile[j][tx] = (w > SPARSITY ? 1.0f : 0.0f) + (w < -SPARSITY ? -1.0f : 0.0f);
    }
    __syncthreads();
    #pragma unroll
    for (int j = ty; j < 32; j += 8)
        WT[(size_t)(o0 + j) * DIN + i0 + tx] = __float2half_rn(tile[tx][j]);
}

__global__ void __launch_bounds__(256) xconv_kernel(
    const float* __restrict__ x, __half* __restrict__ x16) {
    const size_t i = ((size_t)blockIdx.x * 256 + threadIdx.x) * 8;
    float4 a = *(const float4*)(x + i);
    float4 b = *(const float4*)(x + i + 4);
    __half2 h[4];
    h[0] = __floats2half2_rn(a.x, a.y);
    h[1] = __floats2half2_rn(a.z, a.w);
    h[2] = __floats2half2_rn(b.x, b.y);
    h[3] = __floats2half2_rn(b.z, b.w);
    *(uint4*)(x16 + i) = *(const uint4*)h;
}

// ============================================================================
// fp16 mma.sync GEMM: C[M,N] = A[M,K] @ B[N,K]^T (+bias,relu | *scale->fp16)
// CTA 64(M) x 256(N) x 32(K); 256 thr, 8 warps = 2(M) x 4(N), warp 32x64.
// B (fp16 global): 3-stage cp.async. A: fp16 cp.async, or fp32 LDG->cvt->STS.
// ============================================================================
#define TK 32

// fp16 tile row = 32 halves = 64B = 4 chunks of 16B; conflict-free swizzle
__device__ __forceinline__ uint32_t swz16(int row, int c) {
    return (uint32_t)(row * 64 + ((c ^ ((row >> 1) & 3)) << 4));
}
__device__ __forceinline__ void ldsm4(uint32_t& r0, uint32_t& r1, uint32_t& r2,
                                      uint32_t& r3, uint32_t addr) {
    asm volatile("ldmatrix.sync.aligned.m8n8.x4.shared.b16 {%0,%1,%2,%3}, [%4];"
                 : "=r"(r0), "=r"(r1), "=r"(r2), "=r"(r3) : "r"(addr));
}
__device__ __forceinline__ void mma_f16(float* d, uint32_t a0, uint32_t a1,
                                        uint32_t a2, uint32_t a3,
                                        uint32_t b0, uint32_t b1) {
    asm volatile(
        "mma.sync.aligned.m16n8k16.row.col.f32.f16.f16.f32 "
        "{%0,%1,%2,%3}, {%4,%5,%6,%7}, {%8,%9}, {%0,%1,%2,%3};"
        : "+f"(d[0]), "+f"(d[1]), "+f"(d[2]), "+f"(d[3])
        : "r"(a0), "r"(a1), "r"(a2), "r"(a3), "r"(b0), "r"(b1));
}
__device__ __forceinline__ void cpasync16(uint32_t dst, const void* src) {
    asm volatile("cp.async.cg.shared.global [%0], [%1], 16;" :: "r"(dst), "l"(src));
}

#define B_STAGE 16384                       // 256 x 64B
#define A_TILE  4096                        // 64 x 64B

template<int KITERS, bool CONVA, bool RELU, bool F16OUT>
__global__ void __launch_bounds__(256, 2) mm_f16_kernel(
    const void* __restrict__ Abase, size_t batchA, int lda,
    const __half* __restrict__ Bbase, size_t batchB, int ldb,
    void* __restrict__ Cbase, size_t batchC, int ldc,
    const float* __restrict__ bias, float scale)
{
    extern __shared__ char smem[];
    const uint32_t sb = smem_u32(smem);

    const int t    = threadIdx.x;
    const int wid  = t >> 5;
    const int lane = t & 31;
    const int bm   = blockIdx.x * 64;
    const int bn   = blockIdx.y * 256;
    const int b    = blockIdx.z;

    const __half* Bg = Bbase + (size_t)b * batchB;

    const int M0 = (wid & 1) * 32;
    const int N0 = (wid >> 1) * 64;

    // smem layout
    //  CONVA:  B stages [0,3*B_STAGE), A slots [3*B_STAGE, +2*A_TILE)
    //  !CONVA: stage s = [s*(A_TILE+B_STAGE)): A then B
    const uint32_t sA0 = CONVA ? (sb + 3 * B_STAGE) : sb;
    const int     stg  = CONVA ? B_STAGE : (A_TILE + B_STAGE);
    const uint32_t sB0 = CONVA ? sb : (sb + A_TILE);

    // per-thread load coords: row = t>>2, chunk c = t&3
    const int lrow = t >> 2;
    const int lc   = t & 3;

    float acc[2][8][4] = {};
    float4 areg0, areg1;    // CONVA staging (8 fp32)

    auto loadB = [&](int it, int slot) {
        const int k0 = it * TK;
        const uint32_t s0 = sB0 + slot * stg;
        #pragma unroll
        for (int i = 0; i < 4; i++) {
            int idx = t + 256 * i;                  // 0..1023
            int r = idx >> 2, c = idx & 3;
            cpasync16(s0 + swz16(r, c), Bg + (size_t)(bn + r) * ldb + k0 + (c << 3));
        }
    };
    auto loadA16 = [&](int it, int slot) {          // !CONVA
        const __half* Ag = (const __half*)Abase + (size_t)b * batchA;
        const int k0 = it * TK;
        cpasync16(sA0 + slot * stg + swz16(lrow, lc),
                  Ag + (size_t)(bm + lrow) * lda + k0 + (lc << 3));
    };
    auto ldgA32 = [&](int it) {                     // CONVA
        const float* Ag = (const float*)Abase + (size_t)b * batchA;
        const float* p = Ag + (size_t)(bm + lrow) * lda + it * TK + (lc << 3);
        areg0 = *(const float4*)p;
        areg1 = *(const float4*)(p + 4);
    };
    auto stsA32 = [&](int slot) {                   // CONVA: cvt + STS 16B
        __half2 h[4];
        h[0] = __floats2half2_rn(areg0.x, areg0.y);
        h[1] = __floats2half2_rn(areg0.z, areg0.w);
        h[2] = __floats2half2_rn(areg1.x, areg1.y);
        h[3] = __floats2half2_rn(areg1.z, areg1.w);
        *(uint4*)(smem + (sA0 - sb) + slot * A_TILE + swz16(lrow, lc)) =
            *(const uint4*)h;
    };

    // ---- prologue ----
    if (CONVA) {
        ldgA32(0);
        loadB(0, 0); asm volatile("cp.async.commit_group;");
        loadB(1, 1); asm volatile("cp.async.commit_group;");
        stsA32(0);
        ldgA32(1);
    } else {
        loadA16(0, 0); loadB(0, 0); asm volatile("cp.async.commit_group;");
        loadA16(1, 1); loadB(1, 1); asm volatile("cp.async.commit_group;");
    }
    asm volatile("cp.async.wait_group 1;");
    __syncthreads();

    // iter-invariant ldsm lane coords
    const int g = lane >> 3;
    const int l7 = lane & 7;

    for (int it = 0; it < KITERS; it++) {
        // issue next-stage loads
        if (it + 2 < KITERS) {
            if (!CONVA) loadA16(it + 2, (it + 2) % 3);
            loadB(it + 2, CONVA ? ((it + 2) % 3) : ((it + 2) % 3));
        }
        asm volatile("cp.async.commit_group;");

        if (CONVA) {
            stsA32((it + 1) & 1);                  // convert A(it+1) into other slot
            ldgA32(min(it + 2, KITERS - 1));       // prefetch A(it+2)
        }

        const uint32_t abase = CONVA ? (sA0 + (it & 1) * A_TILE)
                                     : (sA0 + (it % 3) * stg);
        const uint32_t bbase = sB0 + (it % 3) * stg;

        #pragma unroll
        for (int ks = 0; ks < 2; ks++) {           // two k16 steps per K32
            uint32_t a[2][4];
            #pragma unroll
            for (int mf = 0; mf < 2; mf++) {
                // x4: m0 rows m0-7 k0-7 | m1 rows m8-15 k0-7 | m2 m0-7 k8-15 | m3 m8-15 k8-15
                int row = M0 + mf * 16 + ((g & 1) << 3) + l7;
                int ch  = ks * 2 + (g >> 1);
                ldsm4(a[mf][0], a[mf][1], a[mf][2], a[mf][3], abase + swz16(row, ch));
            }
            uint32_t bf[8][2];
            #pragma unroll
            for (int j8 = 0; j8 < 4; j8++) {
                // x4: m0 n0-7 k0-7 | m1 n0-7 k8-15 | m2 n8-15 k0-7 | m3 n8-15 k8-15
                int row = N0 + j8 * 16 + ((g >> 1) << 3) + l7;
                int ch  = ks * 2 + (g & 1);
                uint32_t r0, r1, r2, r3;
                ldsm4(r0, r1, r2, r3, bbase + swz16(row, ch));
                bf[j8 * 2 + 0][0] = r0; bf[j8 * 2 + 0][1] = r1;
                bf[j8 * 2 + 1][0] = r2; bf[j8 * 2 + 1][1] = r3;
            }
            #pragma unroll
            for (int mf = 0; mf < 2; mf++)
                #pragma unroll
                for (int nf = 0; nf < 8; nf++)
                    mma_f16(acc[mf][nf], a[mf][0], a[mf][1], a[mf][2], a[mf][3],
                            bf[nf][0], bf[nf][1]);
        }

        asm volatile("cp.async.wait_group 1;");
        __syncthreads();                            // single barrier per iter
    }

    // ---- epilogue ----
    const int rq = lane >> 2;
    const int cq = lane & 3;
    #pragma unroll
    for (int nf = 0; nf < 8; nf++) {
        const int col = bn + N0 + nf * 8 + (cq << 1);
        float2 bv = make_float2(0.f, 0.f);
        if (RELU) bv = *(const float2*)(bias + col);
        #pragma unroll
        for (int mf = 0; mf < 2; mf++) {
            const int row = bm + M0 + mf * 16 + rq;
            float v0 = acc[mf][nf][0] * scale, v1 = acc[mf][nf][1] * scale;
            float v2 = acc[mf][nf][2] * scale, v3 = acc[mf][nf][3] * scale;
            if (RELU) {
                v0 = fmaxf(v0 + bv.x, 0.0f); v1 = fmaxf(v1 + bv.y, 0.0f);
                v2 = fmaxf(v2 + bv.x, 0.0f); v3 = fmaxf(v3 + bv.y, 0.0f);
            }
            if (F16OUT) {
                __half* Cg = (__half*)Cbase + (size_t)b * batchC;
                __half* o0 = Cg + (size_t)row * ldc + col;
                *(__half2*)o0 = __floats2half2_rn(v0, v1);
                *(__half2*)(o0 + 8 * (size_t)ldc) = __floats2half2_rn(v2, v3);
            } else {
                float* Cg = (float*)Cbase + (size_t)b * batchC;
                float* o0 = Cg + (size_t)row * ldc + col;
                *(float2*)o0 = make_float2(v0, v1);
                *(float2*)(o0 + 8 * (size_t)ldc) = make_float2(v2, v3);
            }
        }
    }
}

// ============================================================================
extern "C" void kernel_launch(void* const* d_in, const int* in_sizes, int n_in,
                              void* d_out, int out_size) {
    const float* x      = (const float*)d_in[0];  // [8, 2048, 256]
    const float* adj    = (const float*)d_in[1];  // [8, 2048, 2048]
    const float* weight = (const float*)d_in[2];  // [256, 256]
    const float* bias   = (const float*)d_in[3];  // [256]
    float* out = (float*)d_out;                   // [8, 2048, 256]

    __half *ST, *WT, *X16;
    cudaGetSymbolAddress((void**)&ST, g_ST);
    cudaGetSymbolAddress((void**)&WT, g_WT);
    cudaGetSymbolAddress((void**)&X16, g_X16);

    // prep
    quantW_kernel<<<dim3(DOUT / 32, DIN / 32), dim3(32, 8)>>>(weight, WT);
    xconv_kernel<<<(BATCH * NN * DIN) / (256 * 8), 256>>>(x, X16);

    // GEMM1: ST[b] = (signW @ x[b]^T) * s : M=256, N=2048, K=256, fp16 out
    {
        auto k = mm_f16_kernel<DIN / TK, false, false, true>;
        const int sm = 3 * (A_TILE + B_STAGE);
        cudaFuncSetAttribute(k, cudaFuncAttributeMaxDynamicSharedMemorySize, sm);
        dim3 grid(DOUT / 64, NN / 256, BATCH);
        k<<<grid, 256, sm>>>(
            WT, 0, DIN,
            X16, (size_t)NN * DIN, DIN,
            ST, (size_t)DOUT * NN, NN,
            nullptr, SPARSITY);
    }
    // GEMM2: out[b] = relu(adj[b] @ ST[b]^T + bias) : M=2048, N=256, K=2048
    {
        auto k = mm_f16_kernel<NN / TK, true, true, false>;
        const int sm = 3 * B_STAGE + 2 * A_TILE;
        cudaFuncSetAttribute(k, cudaFuncAttributeMaxDynamicSharedMemorySize, sm);
        dim3 grid(NN / 64, DOUT / 256, BATCH);
        k<<<grid, 256, sm>>>(
            adj, (size_t)NN * NN, NN,
            ST, (size_t)DOUT * NN, NN,
            out, (size_t)NN * DOUT, DOUT,
            bias, 1.0f);
    }
}